// round 1
// baseline (speedup 1.0000x reference)
#include <cuda_runtime.h>
#include <math.h>
#include <stdint.h>

// Problem constants (fixed by setup_inputs)
#define BATCH 2
#define TSEQ  2048
#define DMOD  2048
#define NHEAD 16
#define DHEAD 128
#define MROWS (BATCH * TSEQ)        // 4096
#define QKVN  (3 * DMOD)            // 6144

// ---------------------------------------------------------------------------
// Scratch (static device globals; no runtime allocation)
// ---------------------------------------------------------------------------
__device__ float g_qkv[(size_t)MROWS * QKVN];                 // [4096, 6144]
__device__ float g_q[(size_t)BATCH * NHEAD * TSEQ * DHEAD];   // [B,H,T,d]
__device__ float g_k[(size_t)BATCH * NHEAD * TSEQ * DHEAD];
__device__ float g_v[(size_t)BATCH * NHEAD * TSEQ * DHEAD];
__device__ float g_o[(size_t)BATCH * NHEAD * TSEQ * DHEAD];   // attn out
__device__ float g_g[(size_t)MROWS * DMOD];                   // gated, [B,T,D]

// ---------------------------------------------------------------------------
// SGEMM: C[M,N] = A[M,K] @ B[K,N], fp32 row-major.
// BM=BN=128, BK=16, 256 threads, 8x8 micro-tile per thread.
// mode 0: plain store. mode 1: C = sigmoid(acc + bias[n]) * gateO(permuted)
// ---------------------------------------------------------------------------
#define BM 128
#define BN 128
#define BK 16
#define TM 8
#define TN 8

__global__ void __launch_bounds__(256)
sgemm_kernel(const float* __restrict__ A, const float* __restrict__ B,
             float* __restrict__ C, int M, int N, int K,
             int mode, const float* __restrict__ bias,
             const float* __restrict__ gateO)
{
    __shared__ float As[BK][BM];
    __shared__ float Bs[BK][BN];

    const int bx = blockIdx.x;          // N tile
    const int by = blockIdx.y;          // M tile
    const int tid = threadIdx.x;
    const int tx = tid & 15;
    const int ty = tid >> 4;

    // A-load mapping: 128 rows x 16 cols, float4 along K
    const int aRow  = tid >> 2;         // 0..63
    const int aCol4 = (tid & 3) << 2;   // 0,4,8,12
    // B-load mapping: 16 rows x 128 cols, float4 along N
    const int bRow = tid >> 5;          // 0..7
    const int bCol = (tid & 31) << 2;   // 0..124

    const float* Ap = A + (size_t)(by * BM) * K;
    const float* Bp = B + (size_t)(bx * BN);

    float acc[TM][TN];
#pragma unroll
    for (int i = 0; i < TM; i++)
#pragma unroll
        for (int j = 0; j < TN; j++) acc[i][j] = 0.f;

    for (int k0 = 0; k0 < K; k0 += BK) {
#pragma unroll
        for (int p = 0; p < 2; p++) {
            int r = aRow + p * 64;
            float4 va = *(const float4*)(Ap + (size_t)r * K + k0 + aCol4);
            As[aCol4 + 0][r] = va.x;
            As[aCol4 + 1][r] = va.y;
            As[aCol4 + 2][r] = va.z;
            As[aCol4 + 3][r] = va.w;
        }
#pragma unroll
        for (int p = 0; p < 2; p++) {
            int r = bRow + p * 8;
            *(float4*)(&Bs[r][bCol]) =
                *(const float4*)(Bp + (size_t)(k0 + r) * N + bCol);
        }
        __syncthreads();

#pragma unroll
        for (int k = 0; k < BK; k++) {
            float ra[TM], rb[TN];
#pragma unroll
            for (int i = 0; i < TM; i++) ra[i] = As[k][ty * TM + i];
#pragma unroll
            for (int j = 0; j < TN; j++) rb[j] = Bs[k][tx * TN + j];
#pragma unroll
            for (int i = 0; i < TM; i++)
#pragma unroll
                for (int j = 0; j < TN; j++)
                    acc[i][j] = fmaf(ra[i], rb[j], acc[i][j]);
        }
        __syncthreads();
    }

    const int cRow0 = by * BM + ty * TM;
    const int cCol0 = bx * BN + tx * TN;

    if (mode == 0) {
#pragma unroll
        for (int i = 0; i < TM; i++) {
            float* cp = C + (size_t)(cRow0 + i) * N + cCol0;
#pragma unroll
            for (int j = 0; j < TN; j += 4) {
                float4 v = make_float4(acc[i][j], acc[i][j+1], acc[i][j+2], acc[i][j+3]);
                *(float4*)(cp + j) = v;
            }
        }
    } else {
        // gate epilogue: m -> (b,t), n -> (h,dd); multiply by attention output
#pragma unroll
        for (int i = 0; i < TM; i++) {
            int m = cRow0 + i;
            int b = m >> 11;            // / TSEQ
            int t = m & (TSEQ - 1);
#pragma unroll
            for (int j = 0; j < TN; j++) {
                int n = cCol0 + j;
                float z = acc[i][j] + bias[n];
                float gte = 1.f / (1.f + expf(-z));
                int h  = n >> 7;
                int dd = n & (DHEAD - 1);
                size_t oidx = (((size_t)(b * NHEAD + h)) * TSEQ + t) * DHEAD + dd;
                C[(size_t)m * N + n] = gte * gateO[oidx];
            }
        }
    }
}

// ---------------------------------------------------------------------------
// RMSNorm + RoPE for q,k (plus v permute). One 128-thread block per (b,h,t).
// ---------------------------------------------------------------------------
__global__ void __launch_bounds__(128)
norm_rope_kernel(const float* __restrict__ qkv,
                 float* __restrict__ Qo, float* __restrict__ Ko,
                 float* __restrict__ Vo)
{
    const int rid = blockIdx.x;          // 0 .. B*H*T-1
    const int t  = rid & (TSEQ - 1);
    const int bh = rid >> 11;            // b*H + h
    const int b  = bh >> 4;
    const int h  = bh & (NHEAD - 1);
    const int i  = threadIdx.x;          // 0..127

    const float* row = qkv + ((size_t)(b * TSEQ + t)) * QKVN + h * DHEAD;
    float qv = row[i];
    float kv = row[DMOD + i];
    float vv = row[2 * DMOD + i];

    float q2 = qv * qv, k2 = kv * kv;
#pragma unroll
    for (int o = 16; o; o >>= 1) {
        q2 += __shfl_xor_sync(0xffffffffu, q2, o);
        k2 += __shfl_xor_sync(0xffffffffu, k2, o);
    }
    __shared__ float rq[4], rk[4];
    if ((i & 31) == 0) { rq[i >> 5] = q2; rk[i >> 5] = k2; }
    __syncthreads();
    float ssq = rq[0] + rq[1] + rq[2] + rq[3];
    float ssk = rk[0] + rk[1] + rk[2] + rk[3];
    float rnq = rsqrtf(ssq * (1.f / DHEAD) + 1e-6f);
    float rnk = rsqrtf(ssk * (1.f / DHEAD) + 1e-6f);

    __shared__ float sq[DHEAD], sk[DHEAD];
    sq[i] = qv * rnq;
    sk[i] = kv * rnk;
    __syncthreads();

    const int j = i & 63;
    // inv_freq = 10000^{-(j/64)}; double precision to keep phase error tiny
    double freq = exp(-((double)j / 64.0) * 9.210340371976184);  // ln(1e4)
    double ang = (double)t * freq;
    double sd, cd;
    sincos(ang, &sd, &cd);
    float s = (float)sd, c = (float)cd;

    float oq, ok;
    if (i < 64) {
        oq = sq[i] * c - sq[i + 64] * s;
        ok = sk[i] * c - sk[i + 64] * s;
    } else {
        oq = sq[i - 64] * s + sq[i] * c;
        ok = sk[i - 64] * s + sk[i] * c;
    }
    size_t oidx = ((size_t)bh * TSEQ + t) * DHEAD + i;
    Qo[oidx] = oq;
    Ko[oidx] = ok;
    Vo[oidx] = vv;
}

// ---------------------------------------------------------------------------
// Flash attention (causal, fp32). Br=Bc=64, 256 threads.
// Q,K staged transposed [d][seq] (stride 68) for conflict-free outer product.
// ---------------------------------------------------------------------------
#define FBR 64
#define FBC 64
#define QKSTR 68   // padded seq stride for transposed Q/K tiles
#define SSTR  68   // padded stride for S tile

__global__ void __launch_bounds__(256)
flash_attn_kernel(const float* __restrict__ Qg, const float* __restrict__ Kg,
                  const float* __restrict__ Vg, float* __restrict__ Og)
{
    extern __shared__ float sm[];
    float* Qt  = sm;                       // [128][68]
    float* Kt  = Qt + DHEAD * QKSTR;       // [128][68]
    float* Vs  = Kt + DHEAD * QKSTR;       // [64][128]
    float* Ssh = Vs + FBC * DHEAD;         // [64][68]

    const int qt = blockIdx.x;
    const int bh = blockIdx.y;
    const int tid = threadIdx.x;
    const int tx = tid & 15, ty = tid >> 4;
    const int r0 = ty * 4;       // S rows owned
    const int c0 = tx * 4;       // S cols owned
    const int dcol = tx * 8;     // O d-cols owned

    const float* Qb = Qg + (size_t)bh * TSEQ * DHEAD;
    const float* Kb = Kg + (size_t)bh * TSEQ * DHEAD;
    const float* Vb = Vg + (size_t)bh * TSEQ * DHEAD;

    // Load Q tile transposed
#pragma unroll
    for (int p = 0; p < 8; p++) {
        int idx = tid + p * 256;
        int r  = idx >> 5;
        int c4 = (idx & 31) << 2;
        float4 v = *(const float4*)(Qb + (size_t)(qt * FBR + r) * DHEAD + c4);
        Qt[(c4 + 0) * QKSTR + r] = v.x;
        Qt[(c4 + 1) * QKSTR + r] = v.y;
        Qt[(c4 + 2) * QKSTR + r] = v.z;
        Qt[(c4 + 3) * QKSTR + r] = v.w;
    }

    float m_i[4], l_i[4], acc[4][8];
#pragma unroll
    for (int i = 0; i < 4; i++) { m_i[i] = -INFINITY; l_i[i] = 0.f; }
#pragma unroll
    for (int i = 0; i < 4; i++)
#pragma unroll
        for (int j = 0; j < 8; j++) acc[i][j] = 0.f;

    const float scale = 0.08838834764831845f;  // 1/sqrt(128)

    for (int kt = 0; kt <= qt; kt++) {
        __syncthreads();  // prior iteration's Ssh/Vs reads done; Qt ready (1st iter via next sync)
        // Load K transposed + V natural
#pragma unroll
        for (int p = 0; p < 8; p++) {
            int idx = tid + p * 256;
            int r  = idx >> 5;
            int c4 = (idx & 31) << 2;
            float4 kvv = *(const float4*)(Kb + (size_t)(kt * FBC + r) * DHEAD + c4);
            Kt[(c4 + 0) * QKSTR + r] = kvv.x;
            Kt[(c4 + 1) * QKSTR + r] = kvv.y;
            Kt[(c4 + 2) * QKSTR + r] = kvv.z;
            Kt[(c4 + 3) * QKSTR + r] = kvv.w;
            float4 vvv = *(const float4*)(Vb + (size_t)(kt * FBC + r) * DHEAD + c4);
            *(float4*)(Vs + r * DHEAD + c4) = vvv;
        }
        __syncthreads();

        // S = scale * Q K^T (4x4 per thread)
        float s[4][4];
#pragma unroll
        for (int i = 0; i < 4; i++)
#pragma unroll
            for (int j = 0; j < 4; j++) s[i][j] = 0.f;

        for (int k = 0; k < DHEAD; k++) {
            float4 qv = *(const float4*)(Qt + k * QKSTR + r0);
            float4 kv = *(const float4*)(Kt + k * QKSTR + c0);
            float qa[4] = {qv.x, qv.y, qv.z, qv.w};
            float kb[4] = {kv.x, kv.y, kv.z, kv.w};
#pragma unroll
            for (int i = 0; i < 4; i++)
#pragma unroll
                for (int j = 0; j < 4; j++)
                    s[i][j] = fmaf(qa[i], kb[j], s[i][j]);
        }
#pragma unroll
        for (int i = 0; i < 4; i++)
#pragma unroll
            for (int j = 0; j < 4; j++) s[i][j] *= scale;

        // causal mask on diagonal tile
        if (kt == qt) {
#pragma unroll
            for (int i = 0; i < 4; i++) {
                int rg = r0 + i;
#pragma unroll
                for (int j = 0; j < 4; j++) {
                    if (c0 + j > rg) s[i][j] = -INFINITY;
                }
            }
        }

        // online softmax (row reductions across tx via 16-lane shfl groups)
        float alpha[4], rsum[4];
#pragma unroll
        for (int i = 0; i < 4; i++) {
            float pm = s[i][0];
#pragma unroll
            for (int j = 1; j < 4; j++) pm = fmaxf(pm, s[i][j]);
#pragma unroll
            for (int o = 8; o; o >>= 1)
                pm = fmaxf(pm, __shfl_xor_sync(0xffffffffu, pm, o));
            float mnew = fmaxf(m_i[i], pm);
            float ps = 0.f;
#pragma unroll
            for (int j = 0; j < 4; j++) {
                s[i][j] = expf(s[i][j] - mnew);
                ps += s[i][j];
            }
#pragma unroll
            for (int o = 8; o; o >>= 1)
                ps += __shfl_xor_sync(0xffffffffu, ps, o);
            alpha[i] = expf(m_i[i] - mnew);
            l_i[i] = l_i[i] * alpha[i] + ps;
            m_i[i] = mnew;
            rsum[i] = ps;
            (void)rsum;
#pragma unroll
            for (int j = 0; j < 8; j++) acc[i][j] *= alpha[i];
        }

        // write P to shared
#pragma unroll
        for (int i = 0; i < 4; i++) {
            float4 pv = make_float4(s[i][0], s[i][1], s[i][2], s[i][3]);
            *(float4*)(Ssh + (r0 + i) * SSTR + c0) = pv;
        }
        __syncthreads();

        // acc += P @ V
        for (int kk = 0; kk < FBC; kk++) {
            float pv[4];
#pragma unroll
            for (int i = 0; i < 4; i++) pv[i] = Ssh[(r0 + i) * SSTR + kk];
            float4 v0 = *(const float4*)(Vs + kk * DHEAD + dcol);
            float4 v1 = *(const float4*)(Vs + kk * DHEAD + dcol + 4);
            float vb[8] = {v0.x, v0.y, v0.z, v0.w, v1.x, v1.y, v1.z, v1.w};
#pragma unroll
            for (int i = 0; i < 4; i++)
#pragma unroll
                for (int j = 0; j < 8; j++)
                    acc[i][j] = fmaf(pv[i], vb[j], acc[i][j]);
        }
    }

    // epilogue: O = acc / l
#pragma unroll
    for (int i = 0; i < 4; i++) {
        float inv = 1.f / l_i[i];
        float* op = Og + (size_t)bh * TSEQ * DHEAD +
                    (size_t)(qt * FBR + r0 + i) * DHEAD + dcol;
#pragma unroll
        for (int j = 0; j < 8; j += 4) {
            float4 v = make_float4(acc[i][j] * inv, acc[i][j+1] * inv,
                                   acc[i][j+2] * inv, acc[i][j+3] * inv);
            *(float4*)(op + j) = v;
        }
    }
}

// ---------------------------------------------------------------------------
// Host launcher
// ---------------------------------------------------------------------------
extern "C" void kernel_launch(void* const* d_in, const int* in_sizes, int n_in,
                              void* d_out, int out_size)
{
    const float* x     = (const float*)d_in[0];
    const float* Wqkv  = (const float*)d_in[1];
    const float* Wout  = (const float*)d_in[2];
    const float* Wgate = (const float*)d_in[3];
    const float* bgate = (const float*)d_in[4];
    // d_in[5]: causal mask (tril) — implemented analytically
    float* out = (float*)d_out;

    float *qkv, *q, *k, *v, *o, *g;
    cudaGetSymbolAddress((void**)&qkv, g_qkv);
    cudaGetSymbolAddress((void**)&q,   g_q);
    cudaGetSymbolAddress((void**)&k,   g_k);
    cudaGetSymbolAddress((void**)&v,   g_v);
    cudaGetSymbolAddress((void**)&o,   g_o);
    cudaGetSymbolAddress((void**)&g,   g_g);

    // 1) QKV GEMM
    sgemm_kernel<<<dim3(QKVN / BN, MROWS / BM), 256>>>(
        x, Wqkv, qkv, MROWS, QKVN, DMOD, 0, nullptr, nullptr);

    // 2) RMSNorm + RoPE + permute
    norm_rope_kernel<<<BATCH * NHEAD * TSEQ, 128>>>(qkv, q, k, v);

    // 3) Flash attention
    size_t shmem = (size_t)(DHEAD * QKSTR * 2 + FBC * DHEAD + FBR * SSTR) * sizeof(float);
    cudaFuncSetAttribute(flash_attn_kernel,
                         cudaFuncAttributeMaxDynamicSharedMemorySize, (int)shmem);
    flash_attn_kernel<<<dim3(TSEQ / FBR, BATCH * NHEAD), 256, shmem>>>(q, k, v, o);

    // 4) gate GEMM with fused sigmoid * attn epilogue -> g (in [B,T,D])
    sgemm_kernel<<<dim3(DMOD / BN, MROWS / BM), 256>>>(
        x, Wgate, g, MROWS, DMOD, DMOD, 1, bgate, o);

    // 5) output GEMM
    sgemm_kernel<<<dim3(DMOD / BN, MROWS / BM), 256>>>(
        g, Wout, out, MROWS, DMOD, DMOD, 0, nullptr, nullptr);
}

// round 2
// speedup vs baseline: 3.1215x; 3.1215x over previous
#include <cuda_runtime.h>
#include <math.h>
#include <stdint.h>

// Problem constants (fixed by setup_inputs)
#define BATCH 2
#define TSEQ  2048
#define DMOD  2048
#define NHEAD 16
#define DHEAD 128
#define MROWS (BATCH * TSEQ)        // 4096
#define QKVN  (3 * DMOD)            // 6144

// ---------------------------------------------------------------------------
// Scratch (static device globals; no runtime allocation)
// ---------------------------------------------------------------------------
__device__ float g_qkv[(size_t)MROWS * QKVN];
__device__ float g_q[(size_t)BATCH * NHEAD * TSEQ * DHEAD];
__device__ float g_k[(size_t)BATCH * NHEAD * TSEQ * DHEAD];
__device__ float g_v[(size_t)BATCH * NHEAD * TSEQ * DHEAD];
__device__ float g_o[(size_t)BATCH * NHEAD * TSEQ * DHEAD];
__device__ float g_g[(size_t)MROWS * DMOD];

// ---------------------------------------------------------------------------
// Helpers: tf32 convert, mma, cp.async
// ---------------------------------------------------------------------------
__device__ __forceinline__ uint32_t f2tf(float x) {
    uint32_t r;
    asm("cvt.rna.tf32.f32 %0, %1;" : "=r"(r) : "f"(x));
    return r;
}

__device__ __forceinline__ void mma_tf32(float* c, const uint32_t* a, const uint32_t* b) {
    asm volatile(
        "mma.sync.aligned.m16n8k8.row.col.f32.tf32.tf32.f32 "
        "{%0,%1,%2,%3},{%4,%5,%6,%7},{%8,%9},{%0,%1,%2,%3};\n"
        : "+f"(c[0]), "+f"(c[1]), "+f"(c[2]), "+f"(c[3])
        : "r"(a[0]), "r"(a[1]), "r"(a[2]), "r"(a[3]), "r"(b[0]), "r"(b[1]));
}

__device__ __forceinline__ void cpa16(void* dst, const void* src) {
    uint32_t d = (uint32_t)__cvta_generic_to_shared(dst);
    asm volatile("cp.async.cg.shared.global [%0], [%1], 16;" :: "r"(d), "l"(src));
}
#define CP_COMMIT() asm volatile("cp.async.commit_group;")
#define CP_WAIT0()  asm volatile("cp.async.wait_group 0;")

// ---------------------------------------------------------------------------
// tf32 GEMM: C[M,N] = A[M,K] @ B[K,N] (fp32 storage).
// BM=BN=128, BK=16, 256 threads; warp grid 4x2, warp tile 32x64.
// mode 0: plain; mode 1: C = sigmoid(acc + bias[n]) * gateO(permuted)
// ---------------------------------------------------------------------------
#define BM 128
#define BN 128
#define BK 16
#define BKP (BK + 4)    // 20  -> A-frag conflict-free
#define BNP (BN + 8)    // 136 -> B-frag conflict-free

__global__ void __launch_bounds__(256, 2)
mm_tf32_kernel(const float* __restrict__ A, const float* __restrict__ B,
               float* __restrict__ C, int M, int N, int K,
               int mode, const float* __restrict__ bias,
               const float* __restrict__ gateO)
{
    __shared__ float As[2][BM][BKP];   // 20.5 KB
    __shared__ float Bs[2][BK][BNP];   // 17.4 KB

    const int bx = blockIdx.x, by = blockIdx.y;
    const int tid = threadIdx.x;
    const int lane = tid & 31;
    const int warp = tid >> 5;
    const int wm = warp >> 1;          // 0..3 -> M offset wm*32
    const int wn = warp & 1;           // 0..1 -> N offset wn*64
    const int g  = lane >> 2;          // 0..7
    const int tg = lane & 3;           // 0..3

    // load mappings
    const int aR0 = tid >> 2;               // 0..63 (2 passes of 64)
    const int aC  = (tid & 3) << 2;         // 0,4,8,12
    const int bR0 = tid >> 5;               // 0..7 (2 passes of 8)
    const int bC  = (tid & 31) << 2;        // 0..124

    const float* Abase = A + (size_t)(by * BM) * K;
    const float* Bbase = B + (size_t)(bx * BN);

    float acc[2][8][4];
#pragma unroll
    for (int im = 0; im < 2; im++)
#pragma unroll
        for (int in = 0; in < 8; in++)
#pragma unroll
            for (int j = 0; j < 4; j++) acc[im][in][j] = 0.f;

    const int KT = K / BK;

    // prologue: stage 0
#pragma unroll
    for (int p = 0; p < 2; p++) {
        int r = aR0 + p * 64;
        cpa16(&As[0][r][aC], Abase + (size_t)r * K + aC);
    }
#pragma unroll
    for (int p = 0; p < 2; p++) {
        int r = bR0 + p * 8;
        cpa16(&Bs[0][r][bC], Bbase + (size_t)r * N + bC);
    }
    CP_COMMIT();
    CP_WAIT0();
    __syncthreads();

    for (int kt = 0; kt < KT; kt++) {
        const int cur = kt & 1;
        if (kt + 1 < KT) {
            const int nxt = cur ^ 1;
            const int k0 = (kt + 1) * BK;
#pragma unroll
            for (int p = 0; p < 2; p++) {
                int r = aR0 + p * 64;
                cpa16(&As[nxt][r][aC], Abase + (size_t)r * K + k0 + aC);
            }
#pragma unroll
            for (int p = 0; p < 2; p++) {
                int r = bR0 + p * 8;
                cpa16(&Bs[nxt][r][bC], Bbase + (size_t)(k0 + r) * N + bC);
            }
            CP_COMMIT();
        }

        // compute on cur
#pragma unroll
        for (int ik = 0; ik < 2; ik++) {
            uint32_t afr[2][4];
#pragma unroll
            for (int im = 0; im < 2; im++) {
                int r = wm * 32 + im * 16 + g;
                int c = ik * 8 + tg;
                afr[im][0] = f2tf(As[cur][r][c]);
                afr[im][1] = f2tf(As[cur][r + 8][c]);
                afr[im][2] = f2tf(As[cur][r][c + 4]);
                afr[im][3] = f2tf(As[cur][r + 8][c + 4]);
            }
            uint32_t bfr[8][2];
#pragma unroll
            for (int in = 0; in < 8; in++) {
                int cc = wn * 64 + in * 8 + g;
                int rk = ik * 8 + tg;
                bfr[in][0] = f2tf(Bs[cur][rk][cc]);
                bfr[in][1] = f2tf(Bs[cur][rk + 4][cc]);
            }
#pragma unroll
            for (int im = 0; im < 2; im++)
#pragma unroll
                for (int in = 0; in < 8; in++)
                    mma_tf32(acc[im][in], afr[im], bfr[in]);
        }

        if (kt + 1 < KT) CP_WAIT0();
        __syncthreads();
    }

    // epilogue
    if (mode == 0) {
#pragma unroll
        for (int im = 0; im < 2; im++) {
            int r = by * BM + wm * 32 + im * 16 + g;
#pragma unroll
            for (int in = 0; in < 8; in++) {
                int c = bx * BN + wn * 64 + in * 8 + 2 * tg;
                float2* p0 = (float2*)(C + (size_t)r * N + c);
                float2* p1 = (float2*)(C + (size_t)(r + 8) * N + c);
                *p0 = make_float2(acc[im][in][0], acc[im][in][1]);
                *p1 = make_float2(acc[im][in][2], acc[im][in][3]);
            }
        }
    } else {
#pragma unroll
        for (int im = 0; im < 2; im++) {
            int rbase = by * BM + wm * 32 + im * 16 + g;
#pragma unroll
            for (int in = 0; in < 8; in++) {
                int cbase = bx * BN + wn * 64 + in * 8 + 2 * tg;
#pragma unroll
                for (int e = 0; e < 4; e++) {
                    int r = rbase + (e >> 1) * 8;
                    int c = cbase + (e & 1);
                    int b = r >> 11;
                    int t = r & (TSEQ - 1);
                    float z = acc[im][in][e] + bias[c];
                    float gte = 1.f / (1.f + expf(-z));
                    int h = c >> 7;
                    int dd = c & (DHEAD - 1);
                    size_t oidx = (((size_t)(b * NHEAD + h)) * TSEQ + t) * DHEAD + dd;
                    C[(size_t)r * N + c] = gte * gateO[oidx];
                }
            }
        }
    }
}

// ---------------------------------------------------------------------------
// RMSNorm + RoPE for q,k (plus v permute). One 128-thread block per (b,h,t).
// ---------------------------------------------------------------------------
__global__ void __launch_bounds__(128)
norm_rope_kernel(const float* __restrict__ qkv,
                 float* __restrict__ Qo, float* __restrict__ Ko,
                 float* __restrict__ Vo)
{
    const int rid = blockIdx.x;
    const int t  = rid & (TSEQ - 1);
    const int bh = rid >> 11;
    const int b  = bh >> 4;
    const int h  = bh & (NHEAD - 1);
    const int i  = threadIdx.x;

    const float* row = qkv + ((size_t)(b * TSEQ + t)) * QKVN + h * DHEAD;
    float qv = row[i];
    float kv = row[DMOD + i];
    float vv = row[2 * DMOD + i];

    float q2 = qv * qv, k2 = kv * kv;
#pragma unroll
    for (int o = 16; o; o >>= 1) {
        q2 += __shfl_xor_sync(0xffffffffu, q2, o);
        k2 += __shfl_xor_sync(0xffffffffu, k2, o);
    }
    __shared__ float rq[4], rk[4];
    if ((i & 31) == 0) { rq[i >> 5] = q2; rk[i >> 5] = k2; }
    __syncthreads();
    float ssq = rq[0] + rq[1] + rq[2] + rq[3];
    float ssk = rk[0] + rk[1] + rk[2] + rk[3];
    float rnq = rsqrtf(ssq * (1.f / DHEAD) + 1e-6f);
    float rnk = rsqrtf(ssk * (1.f / DHEAD) + 1e-6f);

    __shared__ float sq[DHEAD], sk[DHEAD];
    sq[i] = qv * rnq;
    sk[i] = kv * rnk;
    __syncthreads();

    const int j = i & 63;
    double freq = exp(-((double)j / 64.0) * 9.210340371976184);
    double ang = (double)t * freq;
    double sd, cd;
    sincos(ang, &sd, &cd);
    float s = (float)sd, c = (float)cd;

    float oq, ok;
    if (i < 64) {
        oq = sq[i] * c - sq[i + 64] * s;
        ok = sk[i] * c - sk[i + 64] * s;
    } else {
        oq = sq[i - 64] * s + sq[i] * c;
        ok = sk[i - 64] * s + sk[i] * c;
    }
    size_t oidx = ((size_t)bh * TSEQ + t) * DHEAD + i;
    Qo[oidx] = oq;
    Ko[oidx] = ok;
    Vo[oidx] = vv;
}

// ---------------------------------------------------------------------------
// Flash attention (causal) with tf32 mma. Br=64, Bc=32, 128 threads (4 warps).
// Each warp owns 16 q-rows (one m16 atom). Q fragments register-resident.
// ---------------------------------------------------------------------------
#define ABR 64
#define ABC 32
#define DP  132   // d + 4
#define PP  36    // Bc + 4

__global__ void __launch_bounds__(128)
flash_mma_kernel(const float* __restrict__ Qg, const float* __restrict__ Kg,
                 const float* __restrict__ Vg, float* __restrict__ Og)
{
    extern __shared__ float fsm[];
    float* Qs = fsm;                    // [64][132]
    float* Ks = Qs + ABR * DP;          // [32][132]
    float* Vs = Ks + ABC * DP;          // [32][132]
    float* Ps = Vs + ABC * DP;          // [64][36]

    const int qt = (gridDim.x - 1) - blockIdx.x;   // heavy tiles first
    const int bh = blockIdx.y;
    const int tid  = threadIdx.x;
    const int lane = tid & 31;
    const int w    = tid >> 5;          // warp 0..3
    const int g    = lane >> 2;
    const int tg   = lane & 3;

    const float* Qb = Qg + (size_t)bh * TSEQ * DHEAD;
    const float* Kb = Kg + (size_t)bh * TSEQ * DHEAD;
    const float* Vb = Vg + (size_t)bh * TSEQ * DHEAD;

    // stage Q tile (64 x 128)
#pragma unroll
    for (int p = 0; p < 16; p++) {
        int idx = tid + p * 128;
        int r = idx >> 5;
        int c = (idx & 31) << 2;
        float4 v = *(const float4*)(Qb + (size_t)(qt * ABR + r) * DHEAD + c);
        *(float4*)(&Qs[r * DP + c]) = v;
    }
    __syncthreads();

    // register-resident Q fragments: 16 k-atoms x 4
    uint32_t qf[16][4];
    {
        int r = w * 16 + g;
#pragma unroll
        for (int ik = 0; ik < 16; ik++) {
            int c = ik * 8 + tg;
            qf[ik][0] = f2tf(Qs[r * DP + c]);
            qf[ik][1] = f2tf(Qs[(r + 8) * DP + c]);
            qf[ik][2] = f2tf(Qs[r * DP + c + 4]);
            qf[ik][3] = f2tf(Qs[(r + 8) * DP + c + 4]);
        }
    }

    float oacc[16][4];
#pragma unroll
    for (int in = 0; in < 16; in++)
#pragma unroll
        for (int j = 0; j < 4; j++) oacc[in][j] = 0.f;
    float m_i[2] = {-INFINITY, -INFINITY};
    float l_i[2] = {0.f, 0.f};

    const float scale = 0.08838834764831845f;  // 1/sqrt(128)
    const int ktmax = 2 * qt + 2;

    for (int kt = 0; kt < ktmax; kt++) {
        __syncthreads();   // previous tile's K/V reads complete
        // stage K,V (32 x 128 each)
#pragma unroll
        for (int p = 0; p < 8; p++) {
            int idx = tid + p * 128;
            int r = idx >> 5;
            int c = (idx & 31) << 2;
            const float4 kv = *(const float4*)(Kb + (size_t)(kt * ABC + r) * DHEAD + c);
            *(float4*)(&Ks[r * DP + c]) = kv;
            const float4 vv = *(const float4*)(Vb + (size_t)(kt * ABC + r) * DHEAD + c);
            *(float4*)(&Vs[r * DP + c]) = vv;
        }
        __syncthreads();

        // S = Q @ K^T  (warp: 16 x 32)
        float sacc[4][4];
#pragma unroll
        for (int in = 0; in < 4; in++)
#pragma unroll
            for (int j = 0; j < 4; j++) sacc[in][j] = 0.f;

#pragma unroll
        for (int ik = 0; ik < 16; ik++) {
#pragma unroll
            for (int in = 0; in < 4; in++) {
                uint32_t bf[2];
                int srow = in * 8 + g;         // seq within tile
                int dcol = ik * 8 + tg;        // d
                bf[0] = f2tf(Ks[srow * DP + dcol]);
                bf[1] = f2tf(Ks[srow * DP + dcol + 4]);
                mma_tf32(sacc[in], qf[ik], bf);
            }
        }

        // scale + causal mask
        const int rlo = qt * ABR + w * 16 + g;
#pragma unroll
        for (int in = 0; in < 4; in++)
#pragma unroll
            for (int j = 0; j < 4; j++) sacc[in][j] *= scale;

        if (kt >= 2 * qt) {
#pragma unroll
            for (int in = 0; in < 4; in++) {
                int cbase = kt * ABC + in * 8 + 2 * tg;
#pragma unroll
                for (int j = 0; j < 4; j++) {
                    int cg = cbase + (j & 1);
                    int rg = rlo + (j >> 1) * 8;
                    if (cg > rg) sacc[in][j] = -INFINITY;
                }
            }
        }

        // online softmax per owned row (rr=0: row g ; rr=1: row g+8)
        float alpha[2];
#pragma unroll
        for (int rr = 0; rr < 2; rr++) {
            float pm = -INFINITY;
#pragma unroll
            for (int in = 0; in < 4; in++) {
                pm = fmaxf(pm, sacc[in][2 * rr]);
                pm = fmaxf(pm, sacc[in][2 * rr + 1]);
            }
            pm = fmaxf(pm, __shfl_xor_sync(0xffffffffu, pm, 1));
            pm = fmaxf(pm, __shfl_xor_sync(0xffffffffu, pm, 2));
            float mnew = fmaxf(m_i[rr], pm);
            float ps = 0.f;
#pragma unroll
            for (int in = 0; in < 4; in++) {
                float e0 = expf(sacc[in][2 * rr]     - mnew);
                float e1 = expf(sacc[in][2 * rr + 1] - mnew);
                sacc[in][2 * rr] = e0;
                sacc[in][2 * rr + 1] = e1;
                ps += e0 + e1;
            }
            ps += __shfl_xor_sync(0xffffffffu, ps, 1);
            ps += __shfl_xor_sync(0xffffffffu, ps, 2);
            alpha[rr] = expf(m_i[rr] - mnew);
            l_i[rr] = l_i[rr] * alpha[rr] + ps;
            m_i[rr] = mnew;
        }
#pragma unroll
        for (int in = 0; in < 16; in++) {
            oacc[in][0] *= alpha[0]; oacc[in][1] *= alpha[0];
            oacc[in][2] *= alpha[1]; oacc[in][3] *= alpha[1];
        }

        // P -> shared (warp-local rows)
        {
            int r0 = w * 16 + g;
#pragma unroll
            for (int in = 0; in < 4; in++) {
                int c = in * 8 + 2 * tg;
                *(float2*)(&Ps[r0 * PP + c])       = make_float2(sacc[in][0], sacc[in][1]);
                *(float2*)(&Ps[(r0 + 8) * PP + c]) = make_float2(sacc[in][2], sacc[in][3]);
            }
        }
        __syncwarp();

        // O += P @ V   (warp: 16 x 128, k = 32)
#pragma unroll
        for (int ik = 0; ik < 4; ik++) {
            uint32_t af[4];
            int r0 = w * 16 + g;
            int c0 = ik * 8 + tg;
            af[0] = f2tf(Ps[r0 * PP + c0]);
            af[1] = f2tf(Ps[(r0 + 8) * PP + c0]);
            af[2] = f2tf(Ps[r0 * PP + c0 + 4]);
            af[3] = f2tf(Ps[(r0 + 8) * PP + c0 + 4]);
#pragma unroll
            for (int in = 0; in < 16; in++) {
                uint32_t bf[2];
                int krow = ik * 8 + tg;
                int dcol = in * 8 + g;
                bf[0] = f2tf(Vs[krow * DP + dcol]);
                bf[1] = f2tf(Vs[(krow + 4) * DP + dcol]);
                mma_tf32(oacc[in], af, bf);
            }
        }
    }

    // epilogue: divide by l, write
    float inv0 = 1.f / l_i[0];
    float inv1 = 1.f / l_i[1];
    {
        int r = qt * ABR + w * 16 + g;
        float* Ob = Og + (size_t)bh * TSEQ * DHEAD;
#pragma unroll
        for (int in = 0; in < 16; in++) {
            int c = in * 8 + 2 * tg;
            *(float2*)(Ob + (size_t)r * DHEAD + c) =
                make_float2(oacc[in][0] * inv0, oacc[in][1] * inv0);
            *(float2*)(Ob + (size_t)(r + 8) * DHEAD + c) =
                make_float2(oacc[in][2] * inv1, oacc[in][3] * inv1);
        }
    }
}

// ---------------------------------------------------------------------------
// Host launcher
// ---------------------------------------------------------------------------
extern "C" void kernel_launch(void* const* d_in, const int* in_sizes, int n_in,
                              void* d_out, int out_size)
{
    const float* x     = (const float*)d_in[0];
    const float* Wqkv  = (const float*)d_in[1];
    const float* Wout  = (const float*)d_in[2];
    const float* Wgate = (const float*)d_in[3];
    const float* bgate = (const float*)d_in[4];
    float* out = (float*)d_out;

    float *qkv, *q, *k, *v, *o, *g;
    cudaGetSymbolAddress((void**)&qkv, g_qkv);
    cudaGetSymbolAddress((void**)&q,   g_q);
    cudaGetSymbolAddress((void**)&k,   g_k);
    cudaGetSymbolAddress((void**)&v,   g_v);
    cudaGetSymbolAddress((void**)&o,   g_o);
    cudaGetSymbolAddress((void**)&g,   g_g);

    // 1) QKV GEMM (tf32 tensor cores)
    mm_tf32_kernel<<<dim3(QKVN / BN, MROWS / BM), 256>>>(
        x, Wqkv, qkv, MROWS, QKVN, DMOD, 0, nullptr, nullptr);

    // 2) RMSNorm + RoPE + permute
    norm_rope_kernel<<<BATCH * NHEAD * TSEQ, 128>>>(qkv, q, k, v);

    // 3) Flash attention (tf32 mma)
    size_t shmem = (size_t)(ABR * DP + 2 * ABC * DP + ABR * PP) * sizeof(float);
    cudaFuncSetAttribute(flash_mma_kernel,
                         cudaFuncAttributeMaxDynamicSharedMemorySize, (int)shmem);
    flash_mma_kernel<<<dim3(TSEQ / ABR, BATCH * NHEAD), 128, shmem>>>(q, k, v, o);

    // 4) gate GEMM with fused sigmoid * attn epilogue
    mm_tf32_kernel<<<dim3(DMOD / BN, MROWS / BM), 256>>>(
        x, Wgate, g, MROWS, DMOD, DMOD, 1, bgate, o);

    // 5) output GEMM
    mm_tf32_kernel<<<dim3(DMOD / BN, MROWS / BM), 256>>>(
        g, Wout, out, MROWS, DMOD, DMOD, 0, nullptr, nullptr);
}

// round 3
// speedup vs baseline: 3.3616x; 1.0769x over previous
#include <cuda_runtime.h>
#include <math.h>
#include <stdint.h>

// Problem constants (fixed by setup_inputs)
#define BATCH 2
#define TSEQ  2048
#define DMOD  2048
#define NHEAD 16
#define DHEAD 128
#define MROWS (BATCH * TSEQ)        // 4096
#define QKVN  (3 * DMOD)            // 6144

// ---------------------------------------------------------------------------
// Scratch (static device globals; no runtime allocation)
// ---------------------------------------------------------------------------
__device__ float g_qkv[(size_t)MROWS * QKVN];
__device__ float g_q[(size_t)BATCH * NHEAD * TSEQ * DHEAD];
__device__ float g_k[(size_t)BATCH * NHEAD * TSEQ * DHEAD];
__device__ float g_v[(size_t)BATCH * NHEAD * TSEQ * DHEAD];
__device__ float g_o[(size_t)BATCH * NHEAD * TSEQ * DHEAD];
__device__ float g_g[(size_t)MROWS * DMOD];
// tf32-rounded copies of inputs
__device__ float g_xr[(size_t)MROWS * DMOD];
__device__ float g_wqkvr[(size_t)DMOD * QKVN];
__device__ float g_wgater[(size_t)DMOD * DMOD];
__device__ float g_woutr[(size_t)DMOD * DMOD];

// ---------------------------------------------------------------------------
// Helpers
// ---------------------------------------------------------------------------
__device__ __forceinline__ uint32_t f2tf(float x) {
    uint32_t r;
    asm("cvt.rna.tf32.f32 %0, %1;" : "=r"(r) : "f"(x));
    return r;
}

__device__ __forceinline__ void mma_tf32(float* c, const uint32_t* a, const uint32_t* b) {
    asm volatile(
        "mma.sync.aligned.m16n8k8.row.col.f32.tf32.tf32.f32 "
        "{%0,%1,%2,%3},{%4,%5,%6,%7},{%8,%9},{%0,%1,%2,%3};\n"
        : "+f"(c[0]), "+f"(c[1]), "+f"(c[2]), "+f"(c[3])
        : "r"(a[0]), "r"(a[1]), "r"(a[2]), "r"(a[3]), "r"(b[0]), "r"(b[1]));
}

__device__ __forceinline__ void cpa16(void* dst, const void* src) {
    uint32_t d = (uint32_t)__cvta_generic_to_shared(dst);
    asm volatile("cp.async.cg.shared.global [%0], [%1], 16;" :: "r"(d), "l"(src));
}
#define CP_COMMIT() asm volatile("cp.async.commit_group;")
#define CP_WAIT0()  asm volatile("cp.async.wait_group 0;")
#define CP_WAIT1()  asm volatile("cp.async.wait_group 1;")

// ---------------------------------------------------------------------------
// Elementwise tf32 rounding pass (float4 vectorized)
// ---------------------------------------------------------------------------
__global__ void __launch_bounds__(256)
tf32_round_kernel(const float* __restrict__ in, float* __restrict__ out, int n4)
{
    int i = blockIdx.x * blockDim.x + threadIdx.x;
    if (i < n4) {
        float4 v = ((const float4*)in)[i];
        v.x = __uint_as_float(f2tf(v.x));
        v.y = __uint_as_float(f2tf(v.y));
        v.z = __uint_as_float(f2tf(v.z));
        v.w = __uint_as_float(f2tf(v.w));
        ((float4*)out)[i] = v;
    }
}

// ---------------------------------------------------------------------------
// tf32 GEMM: C[M,N] = A[M,K] @ B[K,N] (A,B pre-rounded to tf32 values).
// BM=BN=128, BK=16, 3-stage cp.async ring, 256 threads, warp tile 32x64.
// mode 0: plain store; mode 1: C = round_tf32(sigmoid(acc+bias[n]) * gateO)
// ---------------------------------------------------------------------------
#define BM 128
#define BN 128
#define BK 16
#define BKP (BK + 4)    // 20
#define BNP (BN + 8)    // 136
#define GST 3           // stages

#define AS(s, r, c) Ash[(size_t)(s) * BM * BKP + (r) * BKP + (c)]
#define BS(s, r, c) Bsh[(size_t)(s) * BK * BNP + (r) * BNP + (c)]

__global__ void __launch_bounds__(256, 2)
mm_tf32_kernel(const float* __restrict__ A, const float* __restrict__ B,
               float* __restrict__ C, int M, int N, int K,
               int mode, const float* __restrict__ bias,
               const float* __restrict__ gateO)
{
    extern __shared__ float gsm[];
    float* Ash = gsm;                         // [3][128][20]
    float* Bsh = gsm + GST * BM * BKP;        // [3][16][136]

    const int bx = blockIdx.x, by = blockIdx.y;
    const int tid = threadIdx.x;
    const int lane = tid & 31;
    const int warp = tid >> 5;
    const int wm = warp >> 1;
    const int wn = warp & 1;
    const int g  = lane >> 2;
    const int tg = lane & 3;

    const int aR0 = tid >> 2;
    const int aC  = (tid & 3) << 2;
    const int bR0 = tid >> 5;
    const int bC  = (tid & 31) << 2;

    const float* Abase = A + (size_t)(by * BM) * K;
    const float* Bbase = B + (size_t)(bx * BN);

    float acc[2][8][4];
#pragma unroll
    for (int im = 0; im < 2; im++)
#pragma unroll
        for (int in = 0; in < 8; in++)
#pragma unroll
            for (int j = 0; j < 4; j++) acc[im][in][j] = 0.f;

    const int KT = K / BK;

    // prologue: stages 0,1
#pragma unroll
    for (int s = 0; s < 2; s++) {
        const int k0 = s * BK;
#pragma unroll
        for (int p = 0; p < 2; p++) {
            int r = aR0 + p * 64;
            cpa16(&AS(s, r, aC), Abase + (size_t)r * K + k0 + aC);
        }
#pragma unroll
        for (int p = 0; p < 2; p++) {
            int r = bR0 + p * 8;
            cpa16(&BS(s, r, bC), Bbase + (size_t)(k0 + r) * N + bC);
        }
        CP_COMMIT();
    }

    for (int kt = 0; kt < KT; kt++) {
        const int cur = kt % GST;
        if (kt + 1 < KT) { CP_WAIT1(); } else { CP_WAIT0(); }
        __syncthreads();

        if (kt + 2 < KT) {
            const int nxt = (kt + 2) % GST;
            const int k0 = (kt + 2) * BK;
#pragma unroll
            for (int p = 0; p < 2; p++) {
                int r = aR0 + p * 64;
                cpa16(&AS(nxt, r, aC), Abase + (size_t)r * K + k0 + aC);
            }
#pragma unroll
            for (int p = 0; p < 2; p++) {
                int r = bR0 + p * 8;
                cpa16(&BS(nxt, r, bC), Bbase + (size_t)(k0 + r) * N + bC);
            }
            CP_COMMIT();
        }

        // compute on cur (no conversions: data pre-rounded)
#pragma unroll
        for (int ik = 0; ik < 2; ik++) {
            uint32_t afr[2][4];
#pragma unroll
            for (int im = 0; im < 2; im++) {
                int r = wm * 32 + im * 16 + g;
                int c = ik * 8 + tg;
                afr[im][0] = __float_as_uint(AS(cur, r, c));
                afr[im][1] = __float_as_uint(AS(cur, r + 8, c));
                afr[im][2] = __float_as_uint(AS(cur, r, c + 4));
                afr[im][3] = __float_as_uint(AS(cur, r + 8, c + 4));
            }
            uint32_t bfr[8][2];
#pragma unroll
            for (int in = 0; in < 8; in++) {
                int cc = wn * 64 + in * 8 + g;
                int rk = ik * 8 + tg;
                bfr[in][0] = __float_as_uint(BS(cur, rk, cc));
                bfr[in][1] = __float_as_uint(BS(cur, rk + 4, cc));
            }
#pragma unroll
            for (int im = 0; im < 2; im++)
#pragma unroll
                for (int in = 0; in < 8; in++)
                    mma_tf32(acc[im][in], afr[im], bfr[in]);
        }
    }

    // epilogue
    if (mode == 0) {
#pragma unroll
        for (int im = 0; im < 2; im++) {
            int r = by * BM + wm * 32 + im * 16 + g;
#pragma unroll
            for (int in = 0; in < 8; in++) {
                int c = bx * BN + wn * 64 + in * 8 + 2 * tg;
                *(float2*)(C + (size_t)r * N + c) =
                    make_float2(acc[im][in][0], acc[im][in][1]);
                *(float2*)(C + (size_t)(r + 8) * N + c) =
                    make_float2(acc[im][in][2], acc[im][in][3]);
            }
        }
    } else {
#pragma unroll
        for (int im = 0; im < 2; im++) {
            int rbase = by * BM + wm * 32 + im * 16 + g;
#pragma unroll
            for (int in = 0; in < 8; in++) {
                int cbase = bx * BN + wn * 64 + in * 8 + 2 * tg;
#pragma unroll
                for (int e = 0; e < 4; e++) {
                    int r = rbase + (e >> 1) * 8;
                    int c = cbase + (e & 1);
                    int b = r >> 11;
                    int t = r & (TSEQ - 1);
                    float z = acc[im][in][e] + bias[c];
                    float gte = 1.f / (1.f + expf(-z));
                    int h = c >> 7;
                    int dd = c & (DHEAD - 1);
                    size_t oidx = (((size_t)(b * NHEAD + h)) * TSEQ + t) * DHEAD + dd;
                    // round: feeds the out-GEMM as A operand
                    C[(size_t)r * N + c] = __uint_as_float(f2tf(gte * gateO[oidx]));
                }
            }
        }
    }
}

// ---------------------------------------------------------------------------
// RMSNorm + RoPE for q,k (plus v permute); outputs tf32-rounded.
// ---------------------------------------------------------------------------
__global__ void __launch_bounds__(128)
norm_rope_kernel(const float* __restrict__ qkv,
                 float* __restrict__ Qo, float* __restrict__ Ko,
                 float* __restrict__ Vo)
{
    const int rid = blockIdx.x;
    const int t  = rid & (TSEQ - 1);
    const int bh = rid >> 11;
    const int b  = bh >> 4;
    const int h  = bh & (NHEAD - 1);
    const int i  = threadIdx.x;

    const float* row = qkv + ((size_t)(b * TSEQ + t)) * QKVN + h * DHEAD;
    float qv = row[i];
    float kv = row[DMOD + i];
    float vv = row[2 * DMOD + i];

    float q2 = qv * qv, k2 = kv * kv;
#pragma unroll
    for (int o = 16; o; o >>= 1) {
        q2 += __shfl_xor_sync(0xffffffffu, q2, o);
        k2 += __shfl_xor_sync(0xffffffffu, k2, o);
    }
    __shared__ float rq[4], rk[4];
    if ((i & 31) == 0) { rq[i >> 5] = q2; rk[i >> 5] = k2; }
    __syncthreads();
    float ssq = rq[0] + rq[1] + rq[2] + rq[3];
    float ssk = rk[0] + rk[1] + rk[2] + rk[3];
    float rnq = rsqrtf(ssq * (1.f / DHEAD) + 1e-6f);
    float rnk = rsqrtf(ssk * (1.f / DHEAD) + 1e-6f);

    __shared__ float sq[DHEAD], sk[DHEAD];
    sq[i] = qv * rnq;
    sk[i] = kv * rnk;
    __syncthreads();

    const int j = i & 63;
    double freq = exp(-((double)j / 64.0) * 9.210340371976184);
    double ang = (double)t * freq;
    double sd, cd;
    sincos(ang, &sd, &cd);
    float s = (float)sd, c = (float)cd;

    float oq, ok;
    if (i < 64) {
        oq = sq[i] * c - sq[i + 64] * s;
        ok = sk[i] * c - sk[i + 64] * s;
    } else {
        oq = sq[i - 64] * s + sq[i] * c;
        ok = sk[i - 64] * s + sk[i] * c;
    }
    size_t oidx = ((size_t)bh * TSEQ + t) * DHEAD + i;
    Qo[oidx] = __uint_as_float(f2tf(oq));
    Ko[oidx] = __uint_as_float(f2tf(ok));
    Vo[oidx] = __uint_as_float(f2tf(vv));
}

// ---------------------------------------------------------------------------
// Flash attention (causal), tf32 mma. Br=128, Bc=32, 256 threads (8 warps),
// double-buffered cp.async K/V, Q fragments register-resident, no cvt in loop.
// ---------------------------------------------------------------------------
#define ABR 128
#define ABC 32
#define DP  132   // d + 4
#define PP  36    // Bc + 4
#define KTF (ABR / ABC)   // 4 kv-tiles per q-tile

#define FQ_OFF 0
#define FK_OFF (ABR * DP)                    // 16896
#define FV_OFF (FK_OFF + 2 * ABC * DP)       // +8448
#define FP_OFF (FV_OFF + 2 * ABC * DP)       // +8448
#define FSM_FLOATS (FP_OFF + ABR * PP)       // +4608 = 38400 floats

__global__ void __launch_bounds__(256)
flash_mma_kernel(const float* __restrict__ Qg, const float* __restrict__ Kg,
                 const float* __restrict__ Vg, float* __restrict__ Og)
{
    extern __shared__ float fsm[];
    float* Qs = fsm + FQ_OFF;
    float* Ps = fsm + FP_OFF;

    const int qt = (gridDim.x - 1) - blockIdx.x;   // heavy tiles first
    const int bh = blockIdx.y;
    const int tid  = threadIdx.x;
    const int lane = tid & 31;
    const int w    = tid >> 5;          // warp 0..7
    const int g    = lane >> 2;
    const int tg   = lane & 3;

    const float* Qb = Qg + (size_t)bh * TSEQ * DHEAD;
    const float* Kb = Kg + (size_t)bh * TSEQ * DHEAD;
    const float* Vb = Vg + (size_t)bh * TSEQ * DHEAD;

    const int ktmax = KTF * (qt + 1);

    // stage Q tile (128 x 128) via cp.async  -> group 0
#pragma unroll
    for (int p = 0; p < 16; p++) {
        int idx = tid + p * 256;
        int r = idx >> 5;
        int c = (idx & 31) << 2;
        cpa16(&Qs[r * DP + c], Qb + (size_t)(qt * ABR + r) * DHEAD + c);
    }
    CP_COMMIT();

    // prefetch kv tile 0 -> group 1
    {
        const float* kp = Kb;
        const float* vp = Vb;
        float* ks = fsm + FK_OFF;
        float* vs = fsm + FV_OFF;
#pragma unroll
        for (int p = 0; p < 4; p++) {
            int idx = tid + p * 256;
            int r = idx >> 5;
            int c = (idx & 31) << 2;
            cpa16(&ks[r * DP + c], kp + (size_t)r * DHEAD + c);
            cpa16(&vs[r * DP + c], vp + (size_t)r * DHEAD + c);
        }
        CP_COMMIT();
    }

    CP_WAIT1();           // Q ready (kv0 may still be in flight)
    __syncthreads();

    // register-resident Q fragments (pre-rounded: raw bits)
    uint32_t qf[16][4];
    {
        int r = w * 16 + g;
#pragma unroll
        for (int ik = 0; ik < 16; ik++) {
            int c = ik * 8 + tg;
            qf[ik][0] = __float_as_uint(Qs[r * DP + c]);
            qf[ik][1] = __float_as_uint(Qs[(r + 8) * DP + c]);
            qf[ik][2] = __float_as_uint(Qs[r * DP + c + 4]);
            qf[ik][3] = __float_as_uint(Qs[(r + 8) * DP + c + 4]);
        }
    }

    float oacc[16][4];
#pragma unroll
    for (int in = 0; in < 16; in++)
#pragma unroll
        for (int j = 0; j < 4; j++) oacc[in][j] = 0.f;
    float m_i[2] = {-INFINITY, -INFINITY};
    float l_i[2] = {0.f, 0.f};

    const float scale = 0.08838834764831845f;  // 1/sqrt(128)
    const int rlo = qt * ABR + w * 16 + g;     // global row (rr=0)

    for (int kt = 0; kt < ktmax; kt++) {
        // prefetch kt+1 into other buffer
        if (kt + 1 < ktmax) {
            int s = (kt + 1) & 1;
            const float* kp = Kb + (size_t)(kt + 1) * ABC * DHEAD;
            const float* vp = Vb + (size_t)(kt + 1) * ABC * DHEAD;
            float* ks = fsm + FK_OFF + s * ABC * DP;
            float* vs = fsm + FV_OFF + s * ABC * DP;
#pragma unroll
            for (int p = 0; p < 4; p++) {
                int idx = tid + p * 256;
                int r = idx >> 5;
                int c = (idx & 31) << 2;
                cpa16(&ks[r * DP + c], kp + (size_t)r * DHEAD + c);
                cpa16(&vs[r * DP + c], vp + (size_t)r * DHEAD + c);
            }
            CP_COMMIT();
            CP_WAIT1();
        } else {
            CP_WAIT0();
        }
        __syncthreads();   // cur kv visible; all warps past previous reads

        const float* Ksc = fsm + FK_OFF + (kt & 1) * ABC * DP;
        const float* Vsc = fsm + FV_OFF + (kt & 1) * ABC * DP;

        // S = Q @ K^T  (warp: 16 x 32)
        float sacc[4][4];
#pragma unroll
        for (int in = 0; in < 4; in++)
#pragma unroll
            for (int j = 0; j < 4; j++) sacc[in][j] = 0.f;

#pragma unroll
        for (int ik = 0; ik < 16; ik++) {
#pragma unroll
            for (int in = 0; in < 4; in++) {
                uint32_t bf[2];
                int srow = in * 8 + g;
                int dcol = ik * 8 + tg;
                bf[0] = __float_as_uint(Ksc[srow * DP + dcol]);
                bf[1] = __float_as_uint(Ksc[srow * DP + dcol + 4]);
                mma_tf32(sacc[in], qf[ik], bf);
            }
        }

#pragma unroll
        for (int in = 0; in < 4; in++)
#pragma unroll
            for (int j = 0; j < 4; j++) sacc[in][j] *= scale;

        // causal mask (only tiles at/after the diagonal band)
        if (kt >= KTF * qt) {
#pragma unroll
            for (int in = 0; in < 4; in++) {
                int cbase = kt * ABC + in * 8 + 2 * tg;
#pragma unroll
                for (int j = 0; j < 4; j++) {
                    int cg = cbase + (j & 1);
                    int rg = rlo + (j >> 1) * 8;
                    if (cg > rg) sacc[in][j] = -INFINITY;
                }
            }
        }

        // online softmax per owned row (rr=0: row g ; rr=1: row g+8)
        float alpha[2];
#pragma unroll
        for (int rr = 0; rr < 2; rr++) {
            float pm = -INFINITY;
#pragma unroll
            for (int in = 0; in < 4; in++) {
                pm = fmaxf(pm, sacc[in][2 * rr]);
                pm = fmaxf(pm, sacc[in][2 * rr + 1]);
            }
            pm = fmaxf(pm, __shfl_xor_sync(0xffffffffu, pm, 1));
            pm = fmaxf(pm, __shfl_xor_sync(0xffffffffu, pm, 2));
            float mnew = fmaxf(m_i[rr], pm);
            float ps = 0.f;
#pragma unroll
            for (int in = 0; in < 4; in++) {
                float e0 = __expf(sacc[in][2 * rr]     - mnew);
                float e1 = __expf(sacc[in][2 * rr + 1] - mnew);
                sacc[in][2 * rr] = e0;
                sacc[in][2 * rr + 1] = e1;
                ps += e0 + e1;
            }
            ps += __shfl_xor_sync(0xffffffffu, ps, 1);
            ps += __shfl_xor_sync(0xffffffffu, ps, 2);
            alpha[rr] = __expf(m_i[rr] - mnew);
            l_i[rr] = l_i[rr] * alpha[rr] + ps;
            m_i[rr] = mnew;
        }
#pragma unroll
        for (int in = 0; in < 16; in++) {
            oacc[in][0] *= alpha[0]; oacc[in][1] *= alpha[0];
            oacc[in][2] *= alpha[1]; oacc[in][3] *= alpha[1];
        }

        // P -> shared, rounded once (warp-local rows)
        {
            int r0 = w * 16 + g;
#pragma unroll
            for (int in = 0; in < 4; in++) {
                int c = in * 8 + 2 * tg;
                *(float2*)(&Ps[r0 * PP + c]) = make_float2(
                    __uint_as_float(f2tf(sacc[in][0])),
                    __uint_as_float(f2tf(sacc[in][1])));
                *(float2*)(&Ps[(r0 + 8) * PP + c]) = make_float2(
                    __uint_as_float(f2tf(sacc[in][2])),
                    __uint_as_float(f2tf(sacc[in][3])));
            }
        }
        __syncwarp();

        // O += P @ V   (warp: 16 x 128, k = 32)
        {
            int r0 = w * 16 + g;
#pragma unroll
            for (int ik = 0; ik < 4; ik++) {
                uint32_t af[4];
                int c0 = ik * 8 + tg;
                af[0] = __float_as_uint(Ps[r0 * PP + c0]);
                af[1] = __float_as_uint(Ps[(r0 + 8) * PP + c0]);
                af[2] = __float_as_uint(Ps[r0 * PP + c0 + 4]);
                af[3] = __float_as_uint(Ps[(r0 + 8) * PP + c0 + 4]);
#pragma unroll
                for (int in = 0; in < 16; in++) {
                    uint32_t bf[2];
                    int krow = ik * 8 + tg;
                    int dcol = in * 8 + g;
                    bf[0] = __float_as_uint(Vsc[krow * DP + dcol]);
                    bf[1] = __float_as_uint(Vsc[(krow + 4) * DP + dcol]);
                    mma_tf32(oacc[in], af, bf);
                }
            }
        }
        __syncthreads();   // all warps done reading cur before it is refilled
    }

    // epilogue
    float inv0 = 1.f / l_i[0];
    float inv1 = 1.f / l_i[1];
    {
        int r = qt * ABR + w * 16 + g;
        float* Ob = Og + (size_t)bh * TSEQ * DHEAD;
#pragma unroll
        for (int in = 0; in < 16; in++) {
            int c = in * 8 + 2 * tg;
            *(float2*)(Ob + (size_t)r * DHEAD + c) =
                make_float2(oacc[in][0] * inv0, oacc[in][1] * inv0);
            *(float2*)(Ob + (size_t)(r + 8) * DHEAD + c) =
                make_float2(oacc[in][2] * inv1, oacc[in][3] * inv1);
        }
    }
}

// ---------------------------------------------------------------------------
// Host launcher
// ---------------------------------------------------------------------------
extern "C" void kernel_launch(void* const* d_in, const int* in_sizes, int n_in,
                              void* d_out, int out_size)
{
    const float* x     = (const float*)d_in[0];
    const float* Wqkv  = (const float*)d_in[1];
    const float* Wout  = (const float*)d_in[2];
    const float* Wgate = (const float*)d_in[3];
    const float* bgate = (const float*)d_in[4];
    float* out = (float*)d_out;

    float *qkv, *q, *k, *v, *o, *g, *xr, *wqkvr, *wgater, *woutr;
    cudaGetSymbolAddress((void**)&qkv,    g_qkv);
    cudaGetSymbolAddress((void**)&q,      g_q);
    cudaGetSymbolAddress((void**)&k,      g_k);
    cudaGetSymbolAddress((void**)&v,      g_v);
    cudaGetSymbolAddress((void**)&o,      g_o);
    cudaGetSymbolAddress((void**)&g,      g_g);
    cudaGetSymbolAddress((void**)&xr,     g_xr);
    cudaGetSymbolAddress((void**)&wqkvr,  g_wqkvr);
    cudaGetSymbolAddress((void**)&wgater, g_wgater);
    cudaGetSymbolAddress((void**)&woutr,  g_woutr);

    // 0) pre-round inputs to tf32 (removes all cvts from hot loops)
    {
        int n4;
        n4 = (MROWS * DMOD) / 4;
        tf32_round_kernel<<<(n4 + 255) / 256, 256>>>(x, xr, n4);
        n4 = (DMOD * QKVN) / 4;
        tf32_round_kernel<<<(n4 + 255) / 256, 256>>>(Wqkv, wqkvr, n4);
        n4 = (DMOD * DMOD) / 4;
        tf32_round_kernel<<<(n4 + 255) / 256, 256>>>(Wgate, wgater, n4);
        tf32_round_kernel<<<(n4 + 255) / 256, 256>>>(Wout, woutr, n4);
    }

    size_t gemm_smem = (size_t)(GST * BM * BKP + GST * BK * BNP) * sizeof(float);
    cudaFuncSetAttribute(mm_tf32_kernel,
                         cudaFuncAttributeMaxDynamicSharedMemorySize, (int)gemm_smem);

    // 1) QKV GEMM
    mm_tf32_kernel<<<dim3(QKVN / BN, MROWS / BM), 256, gemm_smem>>>(
        xr, wqkvr, qkv, MROWS, QKVN, DMOD, 0, nullptr, nullptr);

    // 2) RMSNorm + RoPE + permute (tf32-rounded outputs)
    norm_rope_kernel<<<BATCH * NHEAD * TSEQ, 128>>>(qkv, q, k, v);

    // 3) Flash attention
    size_t fl_smem = (size_t)FSM_FLOATS * sizeof(float);
    cudaFuncSetAttribute(flash_mma_kernel,
                         cudaFuncAttributeMaxDynamicSharedMemorySize, (int)fl_smem);
    flash_mma_kernel<<<dim3(TSEQ / ABR, BATCH * NHEAD), 256, fl_smem>>>(q, k, v, o);

    // 4) gate GEMM with fused sigmoid * attn epilogue (rounded output)
    mm_tf32_kernel<<<dim3(DMOD / BN, MROWS / BM), 256, gemm_smem>>>(
        xr, wgater, g, MROWS, DMOD, DMOD, 1, bgate, o);

    // 5) output GEMM (unrounded final store)
    mm_tf32_kernel<<<dim3(DMOD / BN, MROWS / BM), 256, gemm_smem>>>(
        g, woutr, out, MROWS, DMOD, DMOD, 0, nullptr, nullptr);
}

// round 4
// speedup vs baseline: 3.4864x; 1.0371x over previous
#include <cuda_runtime.h>
#include <math.h>
#include <stdint.h>

// Problem constants (fixed by setup_inputs)
#define BATCH 2
#define TSEQ  2048
#define DMOD  2048
#define NHEAD 16
#define DHEAD 128
#define MROWS (BATCH * TSEQ)        // 4096
#define QKVN  (3 * DMOD)            // 6144

// ---------------------------------------------------------------------------
// Scratch (static device globals; no runtime allocation)
// ---------------------------------------------------------------------------
__device__ float g_qkv[(size_t)MROWS * QKVN];
__device__ float g_q[(size_t)BATCH * NHEAD * TSEQ * DHEAD];
__device__ float g_k[(size_t)BATCH * NHEAD * TSEQ * DHEAD];
__device__ float g_v[(size_t)BATCH * NHEAD * TSEQ * DHEAD];
__device__ float g_o[(size_t)BATCH * NHEAD * TSEQ * DHEAD];
__device__ float g_g[(size_t)MROWS * DMOD];
// tf32-rounded copies of inputs
__device__ float g_xr[(size_t)MROWS * DMOD];
__device__ float g_wqkvr[(size_t)DMOD * QKVN];
__device__ float g_wgater[(size_t)DMOD * DMOD];
__device__ float g_woutr[(size_t)DMOD * DMOD];

// ---------------------------------------------------------------------------
// Helpers
// ---------------------------------------------------------------------------
__device__ __forceinline__ uint32_t f2tf(float x) {
    uint32_t r;
    asm("cvt.rna.tf32.f32 %0, %1;" : "=r"(r) : "f"(x));
    return r;
}

__device__ __forceinline__ void mma_tf32(float* c, const uint32_t* a, const uint32_t* b) {
    asm volatile(
        "mma.sync.aligned.m16n8k8.row.col.f32.tf32.tf32.f32 "
        "{%0,%1,%2,%3},{%4,%5,%6,%7},{%8,%9},{%0,%1,%2,%3};\n"
        : "+f"(c[0]), "+f"(c[1]), "+f"(c[2]), "+f"(c[3])
        : "r"(a[0]), "r"(a[1]), "r"(a[2]), "r"(a[3]), "r"(b[0]), "r"(b[1]));
}

__device__ __forceinline__ void cpa16(void* dst, const void* src) {
    uint32_t d = (uint32_t)__cvta_generic_to_shared(dst);
    asm volatile("cp.async.cg.shared.global [%0], [%1], 16;" :: "r"(d), "l"(src));
}
#define CP_COMMIT() asm volatile("cp.async.commit_group;")
#define CP_WAIT0()  asm volatile("cp.async.wait_group 0;")
#define CP_WAIT1()  asm volatile("cp.async.wait_group 1;")

// ---------------------------------------------------------------------------
// Elementwise tf32 rounding pass (float4 vectorized)
// ---------------------------------------------------------------------------
__global__ void __launch_bounds__(256)
tf32_round_kernel(const float* __restrict__ in, float* __restrict__ out, int n4)
{
    int i = blockIdx.x * blockDim.x + threadIdx.x;
    if (i < n4) {
        float4 v = ((const float4*)in)[i];
        v.x = __uint_as_float(f2tf(v.x));
        v.y = __uint_as_float(f2tf(v.y));
        v.z = __uint_as_float(f2tf(v.z));
        v.w = __uint_as_float(f2tf(v.w));
        ((float4*)out)[i] = v;
    }
}

// ---------------------------------------------------------------------------
// tf32 GEMM: C[M,N] = A[M,K] @ B[K,N] (A,B pre-rounded to tf32 values).
// BM=BN=128, BK=16, 3-stage cp.async ring, 256 threads, warp tile 32x64.
// mode 0: plain store; mode 1: C = round_tf32(sigmoid(acc+bias[n]) * gateO)
// ---------------------------------------------------------------------------
#define BM 128
#define BN 128
#define BK 16
#define BKP (BK + 4)    // 20
#define BNP (BN + 8)    // 136
#define GST 3           // stages

#define AS(s, r, c) Ash[(size_t)(s) * BM * BKP + (r) * BKP + (c)]
#define BS(s, r, c) Bsh[(size_t)(s) * BK * BNP + (r) * BNP + (c)]

__global__ void __launch_bounds__(256, 2)
mm_tf32_kernel(const float* __restrict__ A, const float* __restrict__ B,
               float* __restrict__ C, int M, int N, int K,
               int mode, const float* __restrict__ bias,
               const float* __restrict__ gateO)
{
    extern __shared__ float gsm[];
    float* Ash = gsm;
    float* Bsh = gsm + GST * BM * BKP;

    const int bx = blockIdx.x, by = blockIdx.y;
    const int tid = threadIdx.x;
    const int lane = tid & 31;
    const int warp = tid >> 5;
    const int wm = warp >> 1;
    const int wn = warp & 1;
    const int g  = lane >> 2;
    const int tg = lane & 3;

    const int aR0 = tid >> 2;
    const int aC  = (tid & 3) << 2;
    const int bR0 = tid >> 5;
    const int bC  = (tid & 31) << 2;

    const float* Abase = A + (size_t)(by * BM) * K;
    const float* Bbase = B + (size_t)(bx * BN);

    float acc[2][8][4];
#pragma unroll
    for (int im = 0; im < 2; im++)
#pragma unroll
        for (int in = 0; in < 8; in++)
#pragma unroll
            for (int j = 0; j < 4; j++) acc[im][in][j] = 0.f;

    const int KT = K / BK;

#pragma unroll
    for (int s = 0; s < 2; s++) {
        const int k0 = s * BK;
#pragma unroll
        for (int p = 0; p < 2; p++) {
            int r = aR0 + p * 64;
            cpa16(&AS(s, r, aC), Abase + (size_t)r * K + k0 + aC);
        }
#pragma unroll
        for (int p = 0; p < 2; p++) {
            int r = bR0 + p * 8;
            cpa16(&BS(s, r, bC), Bbase + (size_t)(k0 + r) * N + bC);
        }
        CP_COMMIT();
    }

    for (int kt = 0; kt < KT; kt++) {
        const int cur = kt % GST;
        if (kt + 1 < KT) { CP_WAIT1(); } else { CP_WAIT0(); }
        __syncthreads();

        if (kt + 2 < KT) {
            const int nxt = (kt + 2) % GST;
            const int k0 = (kt + 2) * BK;
#pragma unroll
            for (int p = 0; p < 2; p++) {
                int r = aR0 + p * 64;
                cpa16(&AS(nxt, r, aC), Abase + (size_t)r * K + k0 + aC);
            }
#pragma unroll
            for (int p = 0; p < 2; p++) {
                int r = bR0 + p * 8;
                cpa16(&BS(nxt, r, bC), Bbase + (size_t)(k0 + r) * N + bC);
            }
            CP_COMMIT();
        }

#pragma unroll
        for (int ik = 0; ik < 2; ik++) {
            uint32_t afr[2][4];
#pragma unroll
            for (int im = 0; im < 2; im++) {
                int r = wm * 32 + im * 16 + g;
                int c = ik * 8 + tg;
                afr[im][0] = __float_as_uint(AS(cur, r, c));
                afr[im][1] = __float_as_uint(AS(cur, r + 8, c));
                afr[im][2] = __float_as_uint(AS(cur, r, c + 4));
                afr[im][3] = __float_as_uint(AS(cur, r + 8, c + 4));
            }
            uint32_t bfr[8][2];
#pragma unroll
            for (int in = 0; in < 8; in++) {
                int cc = wn * 64 + in * 8 + g;
                int rk = ik * 8 + tg;
                bfr[in][0] = __float_as_uint(BS(cur, rk, cc));
                bfr[in][1] = __float_as_uint(BS(cur, rk + 4, cc));
            }
#pragma unroll
            for (int im = 0; im < 2; im++)
#pragma unroll
                for (int in = 0; in < 8; in++)
                    mma_tf32(acc[im][in], afr[im], bfr[in]);
        }
    }

    if (mode == 0) {
#pragma unroll
        for (int im = 0; im < 2; im++) {
            int r = by * BM + wm * 32 + im * 16 + g;
#pragma unroll
            for (int in = 0; in < 8; in++) {
                int c = bx * BN + wn * 64 + in * 8 + 2 * tg;
                *(float2*)(C + (size_t)r * N + c) =
                    make_float2(acc[im][in][0], acc[im][in][1]);
                *(float2*)(C + (size_t)(r + 8) * N + c) =
                    make_float2(acc[im][in][2], acc[im][in][3]);
            }
        }
    } else {
#pragma unroll
        for (int im = 0; im < 2; im++) {
            int rbase = by * BM + wm * 32 + im * 16 + g;
#pragma unroll
            for (int in = 0; in < 8; in++) {
                int cbase = bx * BN + wn * 64 + in * 8 + 2 * tg;
#pragma unroll
                for (int e = 0; e < 4; e++) {
                    int r = rbase + (e >> 1) * 8;
                    int c = cbase + (e & 1);
                    int b = r >> 11;
                    int t = r & (TSEQ - 1);
                    float z = acc[im][in][e] + bias[c];
                    float gte = 1.f / (1.f + expf(-z));
                    int h = c >> 7;
                    int dd = c & (DHEAD - 1);
                    size_t oidx = (((size_t)(b * NHEAD + h)) * TSEQ + t) * DHEAD + dd;
                    C[(size_t)r * N + c] = __uint_as_float(f2tf(gte * gateO[oidx]));
                }
            }
        }
    }
}

// ---------------------------------------------------------------------------
// RMSNorm + RoPE for q,k (plus v permute); outputs tf32-rounded.
// Q is pre-scaled by 1/sqrt(d) (folded attention scale).
// ---------------------------------------------------------------------------
__global__ void __launch_bounds__(128)
norm_rope_kernel(const float* __restrict__ qkv,
                 float* __restrict__ Qo, float* __restrict__ Ko,
                 float* __restrict__ Vo)
{
    const int rid = blockIdx.x;
    const int t  = rid & (TSEQ - 1);
    const int bh = rid >> 11;
    const int b  = bh >> 4;
    const int h  = bh & (NHEAD - 1);
    const int i  = threadIdx.x;

    const float* row = qkv + ((size_t)(b * TSEQ + t)) * QKVN + h * DHEAD;
    float qv = row[i];
    float kv = row[DMOD + i];
    float vv = row[2 * DMOD + i];

    float q2 = qv * qv, k2 = kv * kv;
#pragma unroll
    for (int o = 16; o; o >>= 1) {
        q2 += __shfl_xor_sync(0xffffffffu, q2, o);
        k2 += __shfl_xor_sync(0xffffffffu, k2, o);
    }
    __shared__ float rq[4], rk[4];
    if ((i & 31) == 0) { rq[i >> 5] = q2; rk[i >> 5] = k2; }
    __syncthreads();
    float ssq = rq[0] + rq[1] + rq[2] + rq[3];
    float ssk = rk[0] + rk[1] + rk[2] + rk[3];
    float rnq = rsqrtf(ssq * (1.f / DHEAD) + 1e-6f);
    float rnk = rsqrtf(ssk * (1.f / DHEAD) + 1e-6f);

    __shared__ float sq[DHEAD], sk[DHEAD];
    sq[i] = qv * rnq;
    sk[i] = kv * rnk;
    __syncthreads();

    const int j = i & 63;
    double freq = exp(-((double)j / 64.0) * 9.210340371976184);
    double ang = (double)t * freq;
    double sd, cd;
    sincos(ang, &sd, &cd);
    float s = (float)sd, c = (float)cd;

    float oq, ok;
    if (i < 64) {
        oq = sq[i] * c - sq[i + 64] * s;
        ok = sk[i] * c - sk[i + 64] * s;
    } else {
        oq = sq[i - 64] * s + sq[i] * c;
        ok = sk[i - 64] * s + sk[i] * c;
    }
    const float qscale = 0.08838834764831845f;  // 1/sqrt(128), folded into Q
    size_t oidx = ((size_t)bh * TSEQ + t) * DHEAD + i;
    Qo[oidx] = __uint_as_float(f2tf(oq * qscale));
    Ko[oidx] = __uint_as_float(f2tf(ok));
    Vo[oidx] = __uint_as_float(f2tf(vv));
}

// ---------------------------------------------------------------------------
// Flash attention (causal), tf32 mma. Br=128, Bc=64, 256 threads (8 warps),
// double-buffered cp.async K/V. Q staged into the K-buffer region (fragments
// move to registers before K/V streaming starts). Scale pre-folded into Q.
// ---------------------------------------------------------------------------
#define ABR 128
#define ABC 64
#define DP  132   // d + 4
#define PP  68    // Bc + 4
#define KTF (ABR / ABC)   // 2 kv-tiles per q-tile

#define FK_OFF 0                              // [2][64][132] = 16896 floats
#define FV_OFF (2 * ABC * DP)                 // 16896 -> [2][64][132]
#define FP_OFF (FV_OFF + 2 * ABC * DP)        // 33792 -> [128][68] = 8704
#define FSM_FLOATS (FP_OFF + ABR * PP)        // 42496 floats = 169984 B
// Q staging (128x132 = 16896 floats) overlays the K region exactly.

__global__ void __launch_bounds__(256, 1)
flash_mma_kernel(const float* __restrict__ Qg, const float* __restrict__ Kg,
                 const float* __restrict__ Vg, float* __restrict__ Og)
{
    extern __shared__ float fsm[];
    float* Ps = fsm + FP_OFF;

    const int qt = (gridDim.x - 1) - blockIdx.x;   // heavy tiles first
    const int bh = blockIdx.y;
    const int tid  = threadIdx.x;
    const int lane = tid & 31;
    const int w    = tid >> 5;          // warp 0..7
    const int g    = lane >> 2;
    const int tg   = lane & 3;

    const float* Qb = Qg + (size_t)bh * TSEQ * DHEAD;
    const float* Kb = Kg + (size_t)bh * TSEQ * DHEAD;
    const float* Vb = Vg + (size_t)bh * TSEQ * DHEAD;

    const int ktmax = KTF * (qt + 1);

    // --- prologue: stage Q (128x128) into K region, move frags to registers
    {
        float* Qs = fsm;   // overlays K buffers
#pragma unroll
        for (int p = 0; p < 16; p++) {
            int idx = tid + p * 256;
            int r = idx >> 5;
            int c = (idx & 31) << 2;
            cpa16(&Qs[r * DP + c], Qb + (size_t)(qt * ABR + r) * DHEAD + c);
        }
        CP_COMMIT();
        CP_WAIT0();
        __syncthreads();
    }

    uint32_t qf[16][4];
    {
        const float* Qs = fsm;
        int r = w * 16 + g;
#pragma unroll
        for (int ik = 0; ik < 16; ik++) {
            int c = ik * 8 + tg;
            qf[ik][0] = __float_as_uint(Qs[r * DP + c]);
            qf[ik][1] = __float_as_uint(Qs[(r + 8) * DP + c]);
            qf[ik][2] = __float_as_uint(Qs[r * DP + c + 4]);
            qf[ik][3] = __float_as_uint(Qs[(r + 8) * DP + c + 4]);
        }
    }
    __syncthreads();   // everyone done reading Q before K/V overwrite

    // prefetch kv tile 0 into buffer 0
    {
        float* ks = fsm + FK_OFF;
        float* vs = fsm + FV_OFF;
#pragma unroll
        for (int p = 0; p < 8; p++) {
            int idx = tid + p * 256;
            int r = idx >> 5;
            int c = (idx & 31) << 2;
            cpa16(&ks[r * DP + c], Kb + (size_t)r * DHEAD + c);
            cpa16(&vs[r * DP + c], Vb + (size_t)r * DHEAD + c);
        }
        CP_COMMIT();
    }

    float oacc[16][4];
#pragma unroll
    for (int in = 0; in < 16; in++)
#pragma unroll
        for (int j = 0; j < 4; j++) oacc[in][j] = 0.f;
    float m_i[2] = {-INFINITY, -INFINITY};
    float l_i[2] = {0.f, 0.f};

    const int rlo = qt * ABR + w * 16 + g;

    for (int kt = 0; kt < ktmax; kt++) {
        // prefetch kt+1 into the other buffer (freed by end-of-prev-iter sync)
        if (kt + 1 < ktmax) {
            int s = (kt + 1) & 1;
            const float* kp = Kb + (size_t)(kt + 1) * ABC * DHEAD;
            const float* vp = Vb + (size_t)(kt + 1) * ABC * DHEAD;
            float* ks = fsm + FK_OFF + s * ABC * DP;
            float* vs = fsm + FV_OFF + s * ABC * DP;
#pragma unroll
            for (int p = 0; p < 8; p++) {
                int idx = tid + p * 256;
                int r = idx >> 5;
                int c = (idx & 31) << 2;
                cpa16(&ks[r * DP + c], kp + (size_t)r * DHEAD + c);
                cpa16(&vs[r * DP + c], vp + (size_t)r * DHEAD + c);
            }
            CP_COMMIT();
            CP_WAIT1();
        } else {
            CP_WAIT0();
        }
        __syncthreads();

        const float* Ksc = fsm + FK_OFF + (kt & 1) * ABC * DP;
        const float* Vsc = fsm + FV_OFF + (kt & 1) * ABC * DP;

        // S = Q @ K^T  (warp: 16 x 64; 8 n-atoms)
        float sacc[8][4];
#pragma unroll
        for (int in = 0; in < 8; in++)
#pragma unroll
            for (int j = 0; j < 4; j++) sacc[in][j] = 0.f;

#pragma unroll
        for (int ik = 0; ik < 16; ik++) {
#pragma unroll
            for (int in = 0; in < 8; in++) {
                uint32_t bf[2];
                int srow = in * 8 + g;
                int dcol = ik * 8 + tg;
                bf[0] = __float_as_uint(Ksc[srow * DP + dcol]);
                bf[1] = __float_as_uint(Ksc[srow * DP + dcol + 4]);
                mma_tf32(sacc[in], qf[ik], bf);
            }
        }

        // causal mask (band tiles only)
        if (kt >= KTF * qt) {
#pragma unroll
            for (int in = 0; in < 8; in++) {
                int cbase = kt * ABC + in * 8 + 2 * tg;
#pragma unroll
                for (int j = 0; j < 4; j++) {
                    int cg = cbase + (j & 1);
                    int rg = rlo + (j >> 1) * 8;
                    if (cg > rg) sacc[in][j] = -INFINITY;
                }
            }
        }

        // online softmax per owned row (rr=0: row g ; rr=1: row g+8)
        float alpha[2];
#pragma unroll
        for (int rr = 0; rr < 2; rr++) {
            float pm = -INFINITY;
#pragma unroll
            for (int in = 0; in < 8; in++) {
                pm = fmaxf(pm, sacc[in][2 * rr]);
                pm = fmaxf(pm, sacc[in][2 * rr + 1]);
            }
            pm = fmaxf(pm, __shfl_xor_sync(0xffffffffu, pm, 1));
            pm = fmaxf(pm, __shfl_xor_sync(0xffffffffu, pm, 2));
            float mnew = fmaxf(m_i[rr], pm);
            float ps = 0.f;
#pragma unroll
            for (int in = 0; in < 8; in++) {
                float e0 = __expf(sacc[in][2 * rr]     - mnew);
                float e1 = __expf(sacc[in][2 * rr + 1] - mnew);
                sacc[in][2 * rr] = e0;
                sacc[in][2 * rr + 1] = e1;
                ps += e0 + e1;
            }
            ps += __shfl_xor_sync(0xffffffffu, ps, 1);
            ps += __shfl_xor_sync(0xffffffffu, ps, 2);
            alpha[rr] = __expf(m_i[rr] - mnew);
            l_i[rr] = l_i[rr] * alpha[rr] + ps;
            m_i[rr] = mnew;
        }
#pragma unroll
        for (int in = 0; in < 16; in++) {
            oacc[in][0] *= alpha[0]; oacc[in][1] *= alpha[0];
            oacc[in][2] *= alpha[1]; oacc[in][3] *= alpha[1];
        }

        // P -> shared, rounded once (warp-local rows)
        {
            int r0 = w * 16 + g;
#pragma unroll
            for (int in = 0; in < 8; in++) {
                int c = in * 8 + 2 * tg;
                *(float2*)(&Ps[r0 * PP + c]) = make_float2(
                    __uint_as_float(f2tf(sacc[in][0])),
                    __uint_as_float(f2tf(sacc[in][1])));
                *(float2*)(&Ps[(r0 + 8) * PP + c]) = make_float2(
                    __uint_as_float(f2tf(sacc[in][2])),
                    __uint_as_float(f2tf(sacc[in][3])));
            }
        }
        __syncwarp();

        // O += P @ V   (warp: 16 x 128, k = 64)
        {
            int r0 = w * 16 + g;
#pragma unroll
            for (int ik = 0; ik < 8; ik++) {
                uint32_t af[4];
                int c0 = ik * 8 + tg;
                af[0] = __float_as_uint(Ps[r0 * PP + c0]);
                af[1] = __float_as_uint(Ps[(r0 + 8) * PP + c0]);
                af[2] = __float_as_uint(Ps[r0 * PP + c0 + 4]);
                af[3] = __float_as_uint(Ps[(r0 + 8) * PP + c0 + 4]);
#pragma unroll
                for (int in = 0; in < 16; in++) {
                    uint32_t bf[2];
                    int krow = ik * 8 + tg;
                    int dcol = in * 8 + g;
                    bf[0] = __float_as_uint(Vsc[krow * DP + dcol]);
                    bf[1] = __float_as_uint(Vsc[(krow + 4) * DP + dcol]);
                    mma_tf32(oacc[in], af, bf);
                }
            }
        }
        __syncthreads();   // all warps done reading cur buffer before refill
    }

    // epilogue
    float inv0 = 1.f / l_i[0];
    float inv1 = 1.f / l_i[1];
    {
        int r = qt * ABR + w * 16 + g;
        float* Ob = Og + (size_t)bh * TSEQ * DHEAD;
#pragma unroll
        for (int in = 0; in < 16; in++) {
            int c = in * 8 + 2 * tg;
            *(float2*)(Ob + (size_t)r * DHEAD + c) =
                make_float2(oacc[in][0] * inv0, oacc[in][1] * inv0);
            *(float2*)(Ob + (size_t)(r + 8) * DHEAD + c) =
                make_float2(oacc[in][2] * inv1, oacc[in][3] * inv1);
        }
    }
}

// ---------------------------------------------------------------------------
// Host launcher
// ---------------------------------------------------------------------------
extern "C" void kernel_launch(void* const* d_in, const int* in_sizes, int n_in,
                              void* d_out, int out_size)
{
    const float* x     = (const float*)d_in[0];
    const float* Wqkv  = (const float*)d_in[1];
    const float* Wout  = (const float*)d_in[2];
    const float* Wgate = (const float*)d_in[3];
    const float* bgate = (const float*)d_in[4];
    float* out = (float*)d_out;

    float *qkv, *q, *k, *v, *o, *g, *xr, *wqkvr, *wgater, *woutr;
    cudaGetSymbolAddress((void**)&qkv,    g_qkv);
    cudaGetSymbolAddress((void**)&q,      g_q);
    cudaGetSymbolAddress((void**)&k,      g_k);
    cudaGetSymbolAddress((void**)&v,      g_v);
    cudaGetSymbolAddress((void**)&o,      g_o);
    cudaGetSymbolAddress((void**)&g,      g_g);
    cudaGetSymbolAddress((void**)&xr,     g_xr);
    cudaGetSymbolAddress((void**)&wqkvr,  g_wqkvr);
    cudaGetSymbolAddress((void**)&wgater, g_wgater);
    cudaGetSymbolAddress((void**)&woutr,  g_woutr);

    // 0) pre-round inputs to tf32
    {
        int n4;
        n4 = (MROWS * DMOD) / 4;
        tf32_round_kernel<<<(n4 + 255) / 256, 256>>>(x, xr, n4);
        n4 = (DMOD * QKVN) / 4;
        tf32_round_kernel<<<(n4 + 255) / 256, 256>>>(Wqkv, wqkvr, n4);
        n4 = (DMOD * DMOD) / 4;
        tf32_round_kernel<<<(n4 + 255) / 256, 256>>>(Wgate, wgater, n4);
        tf32_round_kernel<<<(n4 + 255) / 256, 256>>>(Wout, woutr, n4);
    }

    size_t gemm_smem = (size_t)(GST * BM * BKP + GST * BK * BNP) * sizeof(float);
    cudaFuncSetAttribute(mm_tf32_kernel,
                         cudaFuncAttributeMaxDynamicSharedMemorySize, (int)gemm_smem);

    // 1) QKV GEMM
    mm_tf32_kernel<<<dim3(QKVN / BN, MROWS / BM), 256, gemm_smem>>>(
        xr, wqkvr, qkv, MROWS, QKVN, DMOD, 0, nullptr, nullptr);

    // 2) RMSNorm + RoPE + permute (tf32-rounded, Q pre-scaled)
    norm_rope_kernel<<<BATCH * NHEAD * TSEQ, 128>>>(qkv, q, k, v);

    // 3) Flash attention
    size_t fl_smem = (size_t)FSM_FLOATS * sizeof(float);
    cudaFuncSetAttribute(flash_mma_kernel,
                         cudaFuncAttributeMaxDynamicSharedMemorySize, (int)fl_smem);
    flash_mma_kernel<<<dim3(TSEQ / ABR, BATCH * NHEAD), 256, fl_smem>>>(q, k, v, o);

    // 4) gate GEMM with fused sigmoid * attn epilogue
    mm_tf32_kernel<<<dim3(DMOD / BN, MROWS / BM), 256, gemm_smem>>>(
        xr, wgater, g, MROWS, DMOD, DMOD, 1, bgate, o);

    // 5) output GEMM
    mm_tf32_kernel<<<dim3(DMOD / BN, MROWS / BM), 256, gemm_smem>>>(
        g, woutr, out, MROWS, DMOD, DMOD, 0, nullptr, nullptr);
}